// round 4
// baseline (speedup 1.0000x reference)
#include <cuda_runtime.h>
#include <cuda_fp16.h>
#include <cstdint>

#define DEVINL __device__ __forceinline__

// Problem dims
static constexpr int Mdim = 8192;   // B*S = 4*2048
static constexpr int Ndim = 8192;   // D_OUT
static constexpr int Kdim = 2048;   // D_IN

// GEMM tiling (sm80-style mma.sync pipeline; tcgen05 unavailable at target sm_103)
static constexpr int BM = 128;
static constexpr int BN = 128;
static constexpr int BK = 64;                       // fp16 elems per chunk = 128 bytes/row
static constexpr int STAGES = 4;
static constexpr int KCHUNKS = Kdim / BK;           // 32
static constexpr int A_BYTES = BM * 128;            // 16384
static constexpr int B_BYTES = BN * 128;            // 16384
static constexpr int STAGE_BYTES = A_BYTES + B_BYTES;       // 32768
static constexpr int SMEM_GEMM = STAGES * STAGE_BYTES;      // 131072

// ------------------- scratch (device globals; no runtime alloc allowed) ----
__device__ __half g_xh[(size_t)Mdim * Kdim];   // x rounded to fp16
__device__ __half g_wq[(size_t)Ndim * Kdim];   // ternary weights in fp16
__device__ float  g_scale[Ndim];

// ------------------- device helpers ---------------------------------------
DEVINL uint32_t smem_u32(const void* p) {
    uint32_t a;
    asm("{ .reg .u64 t; cvta.to.shared.u64 t, %1; cvt.u32.u64 %0, t; }" : "=r"(a) : "l"(p));
    return a;
}
DEVINL uint32_t swz(uint32_t off) { return off ^ ((off >> 3) & 0x70); }

DEVINL void cp_async16(uint32_t s, const void* g) {
    asm volatile("cp.async.cg.shared.global [%0], [%1], 16;" :: "r"(s), "l"(g) : "memory");
}
DEVINL void cp_commit() { asm volatile("cp.async.commit_group;" ::: "memory"); }
template <int N> DEVINL void cp_wait() {
    asm volatile("cp.async.wait_group %0;" :: "n"(N) : "memory");
}

DEVINL void ldsm4(uint32_t* r, uint32_t a) {
    asm volatile("ldmatrix.sync.aligned.m8n8.x4.shared.b16 {%0,%1,%2,%3}, [%4];"
                 : "=r"(r[0]), "=r"(r[1]), "=r"(r[2]), "=r"(r[3]) : "r"(a));
}
DEVINL void mma16816(float* c, const uint32_t* a, uint32_t b0, uint32_t b1) {
    asm volatile(
        "mma.sync.aligned.m16n8k16.row.col.f32.f16.f16.f32 "
        "{%0,%1,%2,%3}, {%4,%5,%6,%7}, {%8,%9}, {%0,%1,%2,%3};"
        : "+f"(c[0]), "+f"(c[1]), "+f"(c[2]), "+f"(c[3])
        : "r"(a[0]), "r"(a[1]), "r"(a[2]), "r"(a[3]), "r"(b0), "r"(b1));
}

DEVINL uint32_t pack2h(float a, float b) {
    __half2 h = __floats2half2_rn(a, b);
    return *reinterpret_cast<uint32_t*>(&h);
}

// ------------------- preproc kernel 1: quantize weight --------------------
// scale[o] = max(mean|w[o,:]|, 1e-5); wq = clip(rint(w/scale), -1, 1) -> fp16
__global__ void __launch_bounds__(256) quant_kernel(
    const float* __restrict__ w, __half* __restrict__ wq, float* __restrict__ scale)
{
    const int row = blockIdx.x;
    const int t = threadIdx.x;
    const float4* wr = reinterpret_cast<const float4*>(w) + (size_t)row * (Kdim / 4);

    float4 v0 = wr[t];
    float4 v1 = wr[t + 256];
    float s = fabsf(v0.x) + fabsf(v0.y) + fabsf(v0.z) + fabsf(v0.w)
            + fabsf(v1.x) + fabsf(v1.y) + fabsf(v1.z) + fabsf(v1.w);
    #pragma unroll
    for (int o = 16; o > 0; o >>= 1) s += __shfl_xor_sync(0xffffffffu, s, o);

    __shared__ float red[8];
    __shared__ float s_bcast;
    if ((t & 31) == 0) red[t >> 5] = s;
    __syncthreads();
    if (t == 0) {
        float acc = 0.f;
        #pragma unroll
        for (int i = 0; i < 8; i++) acc += red[i];
        float sc = fmaxf(acc * (1.0f / Kdim), 1e-5f);
        s_bcast = sc;
        scale[row] = sc;
    }
    __syncthreads();
    const float sc = s_bcast;

    auto q = [&](float x) -> float {
        float r = rintf(__fdiv_rn(x, sc));   // IEEE div + round-half-even matches jnp.round
        return fminf(1.f, fmaxf(-1.f, r));
    };
    uint2* dst = reinterpret_cast<uint2*>(wq) + (size_t)row * (Kdim / 4);
    uint2 o0, o1;
    o0.x = pack2h(q(v0.x), q(v0.y)); o0.y = pack2h(q(v0.z), q(v0.w));
    o1.x = pack2h(q(v1.x), q(v1.y)); o1.y = pack2h(q(v1.z), q(v1.w));
    dst[t] = o0;
    dst[t + 256] = o1;
}

// ------------------- preproc kernel 2: x -> fp16 ---------------------------
__global__ void __launch_bounds__(256) cvt_kernel(
    const float4* __restrict__ x, uint2* __restrict__ xh, int n4)
{
    for (int i = blockIdx.x * 256 + threadIdx.x; i < n4; i += gridDim.x * 256) {
        float4 v = x[i];
        uint2 h;
        h.x = pack2h(v.x, v.y);
        h.y = pack2h(v.z, v.w);
        xh[i] = h;
    }
}

// ------------------- GEMM kernel -------------------------------------------
__global__ void __launch_bounds__(256, 1) bitlinear_gemm(
    const __half* __restrict__ X, const __half* __restrict__ W,
    const float* __restrict__ scale, float* __restrict__ out)
{
    extern __shared__ char smem[];
    const uint32_t sb = smem_u32(smem);
    const int tid = threadIdx.x;
    const int lane = tid & 31, wid = tid >> 5;
    const int wm = wid >> 2, wn = wid & 3;            // 2x4 warp grid, warp tile 64x32
    const int m0 = blockIdx.y * BM, n0 = blockIdx.x * BN;

    // cp.async mapping: thread -> (row, 16B segment); 32 rows per pass, 4 passes per tile
    const int lrow = tid >> 3, seg = tid & 7;
    const __half* gA = X + (size_t)(m0 + lrow) * Kdim + seg * 8;
    const __half* gB = W + (size_t)(n0 + lrow) * Kdim + seg * 8;
    const uint32_t swz_off = swz((uint32_t)(lrow * 128 + seg * 16)); // row&7 invariant under +32

    auto issue = [&](int s, int kc) {
        const uint32_t base = sb + s * STAGE_BYTES + swz_off;
        const __half* a = gA + kc * BK;
        const __half* b = gB + kc * BK;
        #pragma unroll
        for (int p = 0; p < 4; p++) {
            cp_async16(base + p * 4096,         a + (size_t)p * 32 * Kdim);
            cp_async16(base + A_BYTES + p * 4096, b + (size_t)p * 32 * Kdim);
        }
        cp_commit();
    };

    issue(0, 0); issue(1, 1); issue(2, 2);

    // per-lane ldmatrix address components (cutlass TN pattern, plain ldsm both sides)
    const int la7 = lane & 7;
    const int mA  = la7 + (((lane >> 3) & 1) << 3);
    const int khA = (lane >> 4) & 1;
    const int nB  = la7 + (((lane >> 4) & 1) << 3);
    const int khB = (lane >> 3) & 1;
    const uint32_t rowA = (uint32_t)(wm * 64 + mA) * 128;
    const uint32_t rowB = (uint32_t)(wn * 32 + nB) * 128;
    uint32_t colA[4], colB[4];
    #pragma unroll
    for (int ks = 0; ks < 4; ks++) {
        colA[ks] = (uint32_t)((ks * 32 + khA * 16) ^ (la7 << 4));
        colB[ks] = (uint32_t)((ks * 32 + khB * 16) ^ (la7 << 4));
    }

    float c[4][4][4];
    #pragma unroll
    for (int mt = 0; mt < 4; mt++)
        #pragma unroll
        for (int nt = 0; nt < 4; nt++)
            #pragma unroll
            for (int i = 0; i < 4; i++) c[mt][nt][i] = 0.f;

    cp_wait<STAGES - 2>();
    __syncthreads();

    for (int kc = 0; kc < KCHUNKS; kc++) {
        const uint32_t sA = sb + (kc & (STAGES - 1)) * STAGE_BYTES;
        const uint32_t sB = sA + A_BYTES;
        #pragma unroll
        for (int ks = 0; ks < 4; ks++) {
            uint32_t a[4][4], b[2][4];
            #pragma unroll
            for (int mt = 0; mt < 4; mt++)
                ldsm4(a[mt], sA + rowA + mt * 2048 + colA[ks]);
            #pragma unroll
            for (int bt = 0; bt < 2; bt++)
                ldsm4(b[bt], sB + rowB + bt * 2048 + colB[ks]);
            #pragma unroll
            for (int mt = 0; mt < 4; mt++)
                #pragma unroll
                for (int nt = 0; nt < 4; nt++)
                    mma16816(c[mt][nt], a[mt],
                             b[nt >> 1][(nt & 1) * 2], b[nt >> 1][(nt & 1) * 2 + 1]);
        }
        const int kn = kc + STAGES - 1;
        if (kn < KCHUNKS) issue(kn & (STAGES - 1), kn);
        else cp_commit();                       // keep group-count semantics in the tail
        cp_wait<STAGES - 2>();
        __syncthreads();
    }

    // epilogue: apply per-output-column scale in fp32, vectorized float2 stores
    const int g = lane >> 2, t4 = lane & 3;
    #pragma unroll
    for (int nt = 0; nt < 4; nt++) {
        const int ncol = n0 + wn * 32 + nt * 8 + t4 * 2;
        const float2 s2 = *reinterpret_cast<const float2*>(scale + ncol);
        #pragma unroll
        for (int mt = 0; mt < 4; mt++) {
            const int r0 = m0 + wm * 64 + mt * 16 + g;
            float2 v0, v1;
            v0.x = c[mt][nt][0] * s2.x; v0.y = c[mt][nt][1] * s2.y;
            v1.x = c[mt][nt][2] * s2.x; v1.y = c[mt][nt][3] * s2.y;
            *reinterpret_cast<float2*>(out + (size_t)r0 * Ndim + ncol) = v0;
            *reinterpret_cast<float2*>(out + (size_t)(r0 + 8) * Ndim + ncol) = v1;
        }
    }
}

// ------------------- host side ---------------------------------------------
extern "C" void kernel_launch(void* const* d_in, const int* in_sizes, int n_in,
                              void* d_out, int out_size)
{
    const float* x = (const float*)d_in[0];    // [4,2048,2048]
    const float* w = (const float*)d_in[1];    // [8192,2048]
    float* out = (float*)d_out;                // [4,2048,8192]
    (void)in_sizes; (void)n_in; (void)out_size;

    void *p_xh = nullptr, *p_wq = nullptr, *p_scale = nullptr;
    cudaGetSymbolAddress(&p_xh, g_xh);
    cudaGetSymbolAddress(&p_wq, g_wq);
    cudaGetSymbolAddress(&p_scale, g_scale);

    quant_kernel<<<Ndim, 256>>>(w, (__half*)p_wq, (float*)p_scale);
    cvt_kernel<<<2048, 256>>>((const float4*)x, (uint2*)p_xh, (Mdim * Kdim) / 4);

    cudaFuncSetAttribute(bitlinear_gemm, cudaFuncAttributeMaxDynamicSharedMemorySize, SMEM_GEMM);
    dim3 grid(Ndim / BN, Mdim / BM);   // (64, 64)
    bitlinear_gemm<<<grid, 256, SMEM_GEMM>>>(
        (const __half*)p_xh, (const __half*)p_wq, (const float*)p_scale, out);
}

// round 7
// speedup vs baseline: 1.0797x; 1.0797x over previous
#include <cuda_runtime.h>
#include <cuda_fp16.h>
#include <cstdint>

#define DEVINL __device__ __forceinline__

// Problem dims
static constexpr int Mdim = 8192;   // B*S = 4*2048
static constexpr int Ndim = 8192;   // D_OUT
static constexpr int Kdim = 2048;   // D_IN

// GEMM tiling (sm80-style mma.sync pipeline; tcgen05 unavailable at target sm_103)
// Block 128x256, warp tile 64x64 (2x4 warp grid), BK=64, 4-stage cp.async.
static constexpr int BM = 128;
static constexpr int BN = 256;
static constexpr int BK = 64;                       // fp16 elems per chunk = 128 bytes/row
static constexpr int STAGES = 4;
static constexpr int KCHUNKS = Kdim / BK;           // 32
static constexpr int A_BYTES = BM * 128;            // 16384
static constexpr int B_BYTES = BN * 128;            // 32768
static constexpr int STAGE_BYTES = A_BYTES + B_BYTES;       // 49152
static constexpr int SMEM_GEMM = STAGES * STAGE_BYTES;      // 196608
static_assert(SMEM_GEMM <= 232448, "smem too big");

// ------------------- scratch (device globals; no runtime alloc allowed) ----
__device__ __half g_xh[(size_t)Mdim * Kdim];   // x rounded to fp16
__device__ __half g_wq[(size_t)Ndim * Kdim];   // ternary weights in fp16
__device__ float  g_scale[Ndim];

// ------------------- device helpers ---------------------------------------
DEVINL uint32_t smem_u32(const void* p) {
    uint32_t a;
    asm("{ .reg .u64 t; cvta.to.shared.u64 t, %1; cvt.u32.u64 %0, t; }" : "=r"(a) : "l"(p));
    return a;
}
DEVINL uint32_t swz(uint32_t off) { return off ^ ((off >> 3) & 0x70); }

DEVINL void cp_async16(uint32_t s, const void* g) {
    asm volatile("cp.async.cg.shared.global [%0], [%1], 16;" :: "r"(s), "l"(g) : "memory");
}
DEVINL void cp_commit() { asm volatile("cp.async.commit_group;" ::: "memory"); }
template <int N> DEVINL void cp_wait() {
    asm volatile("cp.async.wait_group %0;" :: "n"(N) : "memory");
}

DEVINL void ldsm4(uint32_t* r, uint32_t a) {
    asm volatile("ldmatrix.sync.aligned.m8n8.x4.shared.b16 {%0,%1,%2,%3}, [%4];"
                 : "=r"(r[0]), "=r"(r[1]), "=r"(r[2]), "=r"(r[3]) : "r"(a));
}
DEVINL void mma16816(float* c, const uint32_t* a, uint32_t b0, uint32_t b1) {
    asm volatile(
        "mma.sync.aligned.m16n8k16.row.col.f32.f16.f16.f32 "
        "{%0,%1,%2,%3}, {%4,%5,%6,%7}, {%8,%9}, {%0,%1,%2,%3};"
        : "+f"(c[0]), "+f"(c[1]), "+f"(c[2]), "+f"(c[3])
        : "r"(a[0]), "r"(a[1]), "r"(a[2]), "r"(a[3]), "r"(b0), "r"(b1));
}

DEVINL uint32_t pack2h(float a, float b) {
    __half2 h = __floats2half2_rn(a, b);
    return *reinterpret_cast<uint32_t*>(&h);
}

// ------------------- preproc kernel 1: quantize weight --------------------
// scale[o] = max(mean|w[o,:]|, 1e-5); wq = clip(rint(w/scale), -1, 1) -> fp16
__global__ void __launch_bounds__(256) quant_kernel(
    const float* __restrict__ w, __half* __restrict__ wq, float* __restrict__ scale)
{
    const int row = blockIdx.x;
    const int t = threadIdx.x;
    const float4* wr = reinterpret_cast<const float4*>(w) + (size_t)row * (Kdim / 4);

    float4 v0 = wr[t];
    float4 v1 = wr[t + 256];
    float s = fabsf(v0.x) + fabsf(v0.y) + fabsf(v0.z) + fabsf(v0.w)
            + fabsf(v1.x) + fabsf(v1.y) + fabsf(v1.z) + fabsf(v1.w);
    #pragma unroll
    for (int o = 16; o > 0; o >>= 1) s += __shfl_xor_sync(0xffffffffu, s, o);

    __shared__ float red[8];
    __shared__ float s_bcast;
    if ((t & 31) == 0) red[t >> 5] = s;
    __syncthreads();
    if (t == 0) {
        float acc = 0.f;
        #pragma unroll
        for (int i = 0; i < 8; i++) acc += red[i];
        float sc = fmaxf(acc * (1.0f / Kdim), 1e-5f);
        s_bcast = sc;
        scale[row] = sc;
    }
    __syncthreads();
    const float sc = s_bcast;

    auto q = [&](float x) -> float {
        float r = rintf(__fdiv_rn(x, sc));   // IEEE div + round-half-even matches jnp.round
        return fminf(1.f, fmaxf(-1.f, r));
    };
    uint2* dst = reinterpret_cast<uint2*>(wq) + (size_t)row * (Kdim / 4);
    uint2 o0, o1;
    o0.x = pack2h(q(v0.x), q(v0.y)); o0.y = pack2h(q(v0.z), q(v0.w));
    o1.x = pack2h(q(v1.x), q(v1.y)); o1.y = pack2h(q(v1.z), q(v1.w));
    dst[t] = o0;
    dst[t + 256] = o1;
}

// ------------------- preproc kernel 2: x -> fp16 ---------------------------
__global__ void __launch_bounds__(256) cvt_kernel(
    const float4* __restrict__ x, uint2* __restrict__ xh, int n4)
{
    for (int i = blockIdx.x * 256 + threadIdx.x; i < n4; i += gridDim.x * 256) {
        float4 v = x[i];
        uint2 h;
        h.x = pack2h(v.x, v.y);
        h.y = pack2h(v.z, v.w);
        xh[i] = h;
    }
}

// ------------------- GEMM kernel -------------------------------------------
__global__ void __launch_bounds__(256, 1) bitlinear_gemm(
    const __half* __restrict__ X, const __half* __restrict__ W,
    const float* __restrict__ scale, float* __restrict__ out)
{
    extern __shared__ char smem[];
    const uint32_t sb = smem_u32(smem);
    const int tid = threadIdx.x;
    const int lane = tid & 31, wid = tid >> 5;
    const int wm = wid >> 2, wn = wid & 3;            // 2x4 warp grid, warp tile 64x64
    const int m0 = blockIdx.y * BM, n0 = blockIdx.x * BN;

    // cp.async mapping: thread -> (row, 16B segment); 32 rows per pass
    const int lrow = tid >> 3, seg = tid & 7;
    const __half* gA = X + (size_t)(m0 + lrow) * Kdim + seg * 8;
    const __half* gB = W + (size_t)(n0 + lrow) * Kdim + seg * 8;
    const uint32_t swz_off = swz((uint32_t)(lrow * 128 + seg * 16)); // row&7 invariant under +32

    auto issue = [&](int s, int kc) {
        const uint32_t base = sb + s * STAGE_BYTES + swz_off;
        const __half* a = gA + kc * BK;
        const __half* b = gB + kc * BK;
        #pragma unroll
        for (int p = 0; p < 4; p++)
            cp_async16(base + p * 4096, a + (size_t)p * 32 * Kdim);
        #pragma unroll
        for (int p = 0; p < 8; p++)
            cp_async16(base + A_BYTES + p * 4096, b + (size_t)p * 32 * Kdim);
        cp_commit();
    };

    issue(0, 0); issue(1, 1); issue(2, 2);

    // per-lane ldmatrix address components (cutlass TN pattern, plain ldsm both sides)
    const int la7 = lane & 7;
    const int mA  = la7 + (((lane >> 3) & 1) << 3);
    const int khA = (lane >> 4) & 1;
    const int nB  = la7 + (((lane >> 4) & 1) << 3);
    const int khB = (lane >> 3) & 1;
    const uint32_t rowA = (uint32_t)(wm * 64 + mA) * 128;
    const uint32_t rowB = (uint32_t)(wn * 64 + nB) * 128;
    uint32_t colA[4], colB[4];
    #pragma unroll
    for (int ks = 0; ks < 4; ks++) {
        colA[ks] = (uint32_t)((ks * 32 + khA * 16) ^ (la7 << 4));
        colB[ks] = (uint32_t)((ks * 32 + khB * 16) ^ (la7 << 4));
    }

    float c[4][8][4];
    #pragma unroll
    for (int mt = 0; mt < 4; mt++)
        #pragma unroll
        for (int nt = 0; nt < 8; nt++)
            #pragma unroll
            for (int i = 0; i < 4; i++) c[mt][nt][i] = 0.f;

    cp_wait<STAGES - 2>();
    __syncthreads();

    for (int kc = 0; kc < KCHUNKS; kc++) {
        const uint32_t sA = sb + (kc & (STAGES - 1)) * STAGE_BYTES;
        const uint32_t sB = sA + A_BYTES;
        #pragma unroll
        for (int ks = 0; ks < 4; ks++) {
            uint32_t a[4][4], b[4][4];
            #pragma unroll
            for (int mt = 0; mt < 4; mt++)
                ldsm4(a[mt], sA + rowA + mt * 2048 + colA[ks]);
            #pragma unroll
            for (int bt = 0; bt < 4; bt++)
                ldsm4(b[bt], sB + rowB + bt * 2048 + colB[ks]);
            #pragma unroll
            for (int mt = 0; mt < 4; mt++)
                #pragma unroll
                for (int nt = 0; nt < 8; nt++)
                    mma16816(c[mt][nt], a[mt],
                             b[nt >> 1][(nt & 1) * 2], b[nt >> 1][(nt & 1) * 2 + 1]);
        }
        const int kn = kc + STAGES - 1;
        if (kn < KCHUNKS) issue(kn & (STAGES - 1), kn);
        else cp_commit();                       // keep group-count semantics in the tail
        cp_wait<STAGES - 2>();
        __syncthreads();
    }

    // epilogue: apply per-output-column scale in fp32, vectorized float2 stores
    const int g = lane >> 2, t4 = lane & 3;
    #pragma unroll
    for (int nt = 0; nt < 8; nt++) {
        const int ncol = n0 + wn * 64 + nt * 8 + t4 * 2;
        const float2 s2 = *reinterpret_cast<const float2*>(scale + ncol);
        #pragma unroll
        for (int mt = 0; mt < 4; mt++) {
            const int r0 = m0 + wm * 64 + mt * 16 + g;
            float2 v0, v1;
            v0.x = c[mt][nt][0] * s2.x; v0.y = c[mt][nt][1] * s2.y;
            v1.x = c[mt][nt][2] * s2.x; v1.y = c[mt][nt][3] * s2.y;
            *reinterpret_cast<float2*>(out + (size_t)r0 * Ndim + ncol) = v0;
            *reinterpret_cast<float2*>(out + (size_t)(r0 + 8) * Ndim + ncol) = v1;
        }
    }
}

// ------------------- host side ---------------------------------------------
extern "C" void kernel_launch(void* const* d_in, const int* in_sizes, int n_in,
                              void* d_out, int out_size)
{
    const float* x = (const float*)d_in[0];    // [4,2048,2048]
    const float* w = (const float*)d_in[1];    // [8192,2048]
    float* out = (float*)d_out;                // [4,2048,8192]
    (void)in_sizes; (void)n_in; (void)out_size;

    void *p_xh = nullptr, *p_wq = nullptr, *p_scale = nullptr;
    cudaGetSymbolAddress(&p_xh, g_xh);
    cudaGetSymbolAddress(&p_wq, g_wq);
    cudaGetSymbolAddress(&p_scale, g_scale);

    quant_kernel<<<Ndim, 256>>>(w, (__half*)p_wq, (float*)p_scale);
    cvt_kernel<<<2048, 256>>>((const float4*)x, (uint2*)p_xh, (Mdim * Kdim) / 4);

    cudaFuncSetAttribute(bitlinear_gemm, cudaFuncAttributeMaxDynamicSharedMemorySize, SMEM_GEMM);
    dim3 grid(Ndim / BN, Mdim / BM);   // (32, 64)
    bitlinear_gemm<<<grid, 256, SMEM_GEMM>>>(
        (const __half*)p_xh, (const __half*)p_wq, (const float*)p_scale, out);
}

// round 9
// speedup vs baseline: 1.2328x; 1.1418x over previous
#include <cuda_runtime.h>
#include <cuda_fp16.h>
#include <cstdint>

#define DEVINL __device__ __forceinline__

// Problem dims
static constexpr int Mdim = 8192;   // B*S = 4*2048
static constexpr int Ndim = 8192;   // D_OUT
static constexpr int Kdim = 2048;   // D_IN

// GEMM tiling (sm80-style mma.sync pipeline; tcgen05 unavailable at target sm_103)
// Block 128x256, warp tile 64x64 (2x4 warp grid), BK=64, 4-stage cp.async,
// register-fragment double buffering.
static constexpr int BM = 128;
static constexpr int BN = 256;
static constexpr int BK = 64;                       // fp16 elems per chunk = 128 bytes/row
static constexpr int STAGES = 4;
static constexpr int KCHUNKS = Kdim / BK;           // 32
static constexpr int A_BYTES = BM * 128;            // 16384
static constexpr int B_BYTES = BN * 128;            // 32768
static constexpr int STAGE_BYTES = A_BYTES + B_BYTES;       // 49152
static constexpr int SMEM_GEMM = STAGES * STAGE_BYTES;      // 196608
static_assert(SMEM_GEMM <= 232448, "smem too big");

// ------------------- scratch (device globals; no runtime alloc allowed) ----
__device__ __half g_xh[(size_t)Mdim * Kdim];   // x rounded to fp16
__device__ __half g_wq[(size_t)Ndim * Kdim];   // ternary weights in fp16
__device__ float  g_scale[Ndim];

// ------------------- device helpers ---------------------------------------
DEVINL uint32_t smem_u32(const void* p) {
    uint32_t a;
    asm("{ .reg .u64 t; cvta.to.shared.u64 t, %1; cvt.u32.u64 %0, t; }" : "=r"(a) : "l"(p));
    return a;
}
DEVINL uint32_t swz(uint32_t off) { return off ^ ((off >> 3) & 0x70); }

DEVINL void cp_async16(uint32_t s, const void* g) {
    asm volatile("cp.async.cg.shared.global [%0], [%1], 16;" :: "r"(s), "l"(g) : "memory");
}
DEVINL void cp_commit() { asm volatile("cp.async.commit_group;" ::: "memory"); }
template <int N> DEVINL void cp_wait() {
    asm volatile("cp.async.wait_group %0;" :: "n"(N) : "memory");
}

DEVINL void ldsm4(uint32_t* r, uint32_t a) {
    asm volatile("ldmatrix.sync.aligned.m8n8.x4.shared.b16 {%0,%1,%2,%3}, [%4];"
                 : "=r"(r[0]), "=r"(r[1]), "=r"(r[2]), "=r"(r[3]) : "r"(a));
}
DEVINL void mma16816(float* c, const uint32_t* a, uint32_t b0, uint32_t b1) {
    asm volatile(
        "mma.sync.aligned.m16n8k16.row.col.f32.f16.f16.f32 "
        "{%0,%1,%2,%3}, {%4,%5,%6,%7}, {%8,%9}, {%0,%1,%2,%3};"
        : "+f"(c[0]), "+f"(c[1]), "+f"(c[2]), "+f"(c[3])
        : "r"(a[0]), "r"(a[1]), "r"(a[2]), "r"(a[3]), "r"(b0), "r"(b1));
}

DEVINL uint32_t pack2h(float a, float b) {
    __half2 h = __floats2half2_rn(a, b);
    return *reinterpret_cast<uint32_t*>(&h);
}

// ------------------- preproc kernel 1: quantize weight --------------------
// scale[o] = max(mean|w[o,:]|, 1e-5); wq = clip(rint(w/scale), -1, 1) -> fp16
__global__ void __launch_bounds__(256) quant_kernel(
    const float* __restrict__ w, __half* __restrict__ wq, float* __restrict__ scale)
{
    const int row = blockIdx.x;
    const int t = threadIdx.x;
    const float4* wr = reinterpret_cast<const float4*>(w) + (size_t)row * (Kdim / 4);

    float4 v0 = wr[t];
    float4 v1 = wr[t + 256];
    float s = fabsf(v0.x) + fabsf(v0.y) + fabsf(v0.z) + fabsf(v0.w)
            + fabsf(v1.x) + fabsf(v1.y) + fabsf(v1.z) + fabsf(v1.w);
    #pragma unroll
    for (int o = 16; o > 0; o >>= 1) s += __shfl_xor_sync(0xffffffffu, s, o);

    __shared__ float red[8];
    __shared__ float s_bcast;
    if ((t & 31) == 0) red[t >> 5] = s;
    __syncthreads();
    if (t == 0) {
        float acc = 0.f;
        #pragma unroll
        for (int i = 0; i < 8; i++) acc += red[i];
        float sc = fmaxf(acc * (1.0f / Kdim), 1e-5f);
        s_bcast = sc;
        scale[row] = sc;
    }
    __syncthreads();
    const float sc = s_bcast;

    auto q = [&](float x) -> float {
        float r = rintf(__fdiv_rn(x, sc));   // IEEE div + round-half-even matches jnp.round
        return fminf(1.f, fmaxf(-1.f, r));
    };
    uint2* dst = reinterpret_cast<uint2*>(wq) + (size_t)row * (Kdim / 4);
    uint2 o0, o1;
    o0.x = pack2h(q(v0.x), q(v0.y)); o0.y = pack2h(q(v0.z), q(v0.w));
    o1.x = pack2h(q(v1.x), q(v1.y)); o1.y = pack2h(q(v1.z), q(v1.w));
    dst[t] = o0;
    dst[t + 256] = o1;
}

// ------------------- preproc kernel 2: x -> fp16 ---------------------------
__global__ void __launch_bounds__(256) cvt_kernel(
    const float4* __restrict__ x, uint2* __restrict__ xh, int n4)
{
    for (int i = blockIdx.x * 256 + threadIdx.x; i < n4; i += gridDim.x * 256) {
        float4 v = x[i];
        uint2 h;
        h.x = pack2h(v.x, v.y);
        h.y = pack2h(v.z, v.w);
        xh[i] = h;
    }
}

// ------------------- GEMM kernel -------------------------------------------
__global__ void __launch_bounds__(256, 1) bitlinear_gemm(
    const __half* __restrict__ X, const __half* __restrict__ W,
    const float* __restrict__ scale, float* __restrict__ out)
{
    extern __shared__ char smem[];
    const uint32_t sb = smem_u32(smem);
    const int tid = threadIdx.x;
    const int lane = tid & 31, wid = tid >> 5;
    const int wm = wid >> 2, wn = wid & 3;            // 2x4 warp grid, warp tile 64x64
    const int m0 = blockIdx.y * BM, n0 = blockIdx.x * BN;

    // cp.async mapping: thread -> (row, 16B segment); 32 rows per pass
    const int lrow = tid >> 3, seg = tid & 7;
    const __half* gA = X + (size_t)(m0 + lrow) * Kdim + seg * 8;
    const __half* gB = W + (size_t)(n0 + lrow) * Kdim + seg * 8;
    const uint32_t swz_off = swz((uint32_t)(lrow * 128 + seg * 16)); // row&7 invariant under +32

    auto issue = [&](int s, int kc) {
        const uint32_t base = sb + s * STAGE_BYTES + swz_off;
        const __half* a = gA + kc * BK;
        const __half* b = gB + kc * BK;
        #pragma unroll
        for (int p = 0; p < 4; p++)
            cp_async16(base + p * 4096, a + (size_t)p * 32 * Kdim);
        #pragma unroll
        for (int p = 0; p < 8; p++)
            cp_async16(base + A_BYTES + p * 4096, b + (size_t)p * 32 * Kdim);
        cp_commit();
    };

    issue(0, 0); issue(1, 1); issue(2, 2);

    // per-lane ldmatrix address components (cutlass TN pattern, plain ldsm both sides)
    const int la7 = lane & 7;
    const int mA  = la7 + (((lane >> 3) & 1) << 3);
    const int khA = (lane >> 4) & 1;
    const int nB  = la7 + (((lane >> 4) & 1) << 3);
    const int khB = (lane >> 3) & 1;
    const uint32_t rowA = (uint32_t)(wm * 64 + mA) * 128;
    const uint32_t rowB = (uint32_t)(wn * 64 + nB) * 128;
    uint32_t colA[4], colB[4];
    #pragma unroll
    for (int ks = 0; ks < 4; ks++) {
        colA[ks] = (uint32_t)((ks * 32 + khA * 16) ^ (la7 << 4));
        colB[ks] = (uint32_t)((ks * 32 + khB * 16) ^ (la7 << 4));
    }

    float c[4][8][4];
    #pragma unroll
    for (int mt = 0; mt < 4; mt++)
        #pragma unroll
        for (int nt = 0; nt < 8; nt++)
            #pragma unroll
            for (int i = 0; i < 4; i++) c[mt][nt][i] = 0.f;

    // double-buffered register fragments
    uint32_t af[2][4][4], bf[2][4][4];
    auto ldfrag = [&](int buf, uint32_t sA, uint32_t sB, int ks) {
        #pragma unroll
        for (int mt = 0; mt < 4; mt++)
            ldsm4(af[buf][mt], sA + rowA + mt * 2048 + colA[ks]);
        #pragma unroll
        for (int bt = 0; bt < 4; bt++)
            ldsm4(bf[buf][bt], sB + rowB + bt * 2048 + colB[ks]);
    };

    cp_wait<STAGES - 2>();
    __syncthreads();
    ldfrag(0, sb, sb + A_BYTES, 0);     // stage 0, ks 0

    for (int kc = 0; kc < KCHUNKS; kc++) {
        const uint32_t sA = sb + (kc & (STAGES - 1)) * STAGE_BYTES;
        const uint32_t sB = sA + A_BYTES;
        const uint32_t nA = sb + ((kc + 1) & (STAGES - 1)) * STAGE_BYTES;

        // fill the stage vacated at the end of the previous chunk
        const int kn = kc + STAGES - 1;
        if (kn < KCHUNKS) issue(kn & (STAGES - 1), kn);
        else cp_commit();                         // keep group-count semantics in the tail

        #pragma unroll
        for (int ks = 0; ks < 4; ks++) {
            const int cur = ks & 1, nxt = cur ^ 1;
            if (ks < 3) {
                ldfrag(nxt, sA, sB, ks + 1);
            } else {
                cp_wait<STAGES - 2>();            // next stage resident
                __syncthreads();                  // all smem reads of old stage done
                if (kc + 1 < KCHUNKS)
                    ldfrag(nxt, nA, nA + A_BYTES, 0);
            }
            #pragma unroll
            for (int mt = 0; mt < 4; mt++)
                #pragma unroll
                for (int nt = 0; nt < 8; nt++)
                    mma16816(c[mt][nt], af[cur][mt],
                             bf[cur][nt >> 1][(nt & 1) * 2], bf[cur][nt >> 1][(nt & 1) * 2 + 1]);
        }
    }

    // epilogue: apply per-output-column scale in fp32, vectorized float2 stores
    const int g = lane >> 2, t4 = lane & 3;
    #pragma unroll
    for (int nt = 0; nt < 8; nt++) {
        const int ncol = n0 + wn * 64 + nt * 8 + t4 * 2;
        const float2 s2 = *reinterpret_cast<const float2*>(scale + ncol);
        #pragma unroll
        for (int mt = 0; mt < 4; mt++) {
            const int r0 = m0 + wm * 64 + mt * 16 + g;
            float2 v0, v1;
            v0.x = c[mt][nt][0] * s2.x; v0.y = c[mt][nt][1] * s2.y;
            v1.x = c[mt][nt][2] * s2.x; v1.y = c[mt][nt][3] * s2.y;
            *reinterpret_cast<float2*>(out + (size_t)r0 * Ndim + ncol) = v0;
            *reinterpret_cast<float2*>(out + (size_t)(r0 + 8) * Ndim + ncol) = v1;
        }
    }
}

// ------------------- host side ---------------------------------------------
extern "C" void kernel_launch(void* const* d_in, const int* in_sizes, int n_in,
                              void* d_out, int out_size)
{
    const float* x = (const float*)d_in[0];    // [4,2048,2048]
    const float* w = (const float*)d_in[1];    // [8192,2048]
    float* out = (float*)d_out;                // [4,2048,8192]
    (void)in_sizes; (void)n_in; (void)out_size;

    void *p_xh = nullptr, *p_wq = nullptr, *p_scale = nullptr;
    cudaGetSymbolAddress(&p_xh, g_xh);
    cudaGetSymbolAddress(&p_wq, g_wq);
    cudaGetSymbolAddress(&p_scale, g_scale);

    quant_kernel<<<Ndim, 256>>>(w, (__half*)p_wq, (float*)p_scale);
    cvt_kernel<<<2048, 256>>>((const float4*)x, (uint2*)p_xh, (Mdim * Kdim) / 4);

    cudaFuncSetAttribute(bitlinear_gemm, cudaFuncAttributeMaxDynamicSharedMemorySize, SMEM_GEMM);
    dim3 grid(Ndim / BN, Mdim / BM);   // (32, 64)
    bitlinear_gemm<<<grid, 256, SMEM_GEMM>>>(
        (const __half*)p_xh, (const __half*)p_wq, (const float*)p_scale, out);
}

// round 14
// speedup vs baseline: 1.2424x; 1.0078x over previous
#include <cuda_runtime.h>
#include <cuda_fp16.h>
#include <cstdint>

#define DEVINL __device__ __forceinline__

// Problem dims
static constexpr int Mdim = 8192;   // B*S = 4*2048
static constexpr int Ndim = 8192;   // D_OUT
static constexpr int Kdim = 2048;   // D_IN

// GEMM tiling (sm80-style mma.sync pipeline; tcgen05 unavailable at target sm_103)
// Block 128x256, warp tile 64x64 (2x4 warp grid), BK=64, 4-stage cp.async,
// register-fragment double buffering, barrier moved off the tensor-issue path.
static constexpr int BM = 128;
static constexpr int BN = 256;
static constexpr int BK = 64;                       // fp16 elems per chunk = 128 bytes/row
static constexpr int STAGES = 4;
static constexpr int KCHUNKS = Kdim / BK;           // 32
static constexpr int A_BYTES = BM * 128;            // 16384
static constexpr int B_BYTES = BN * 128;            // 32768
static constexpr int STAGE_BYTES = A_BYTES + B_BYTES;       // 49152
static constexpr int SMEM_GEMM = STAGES * STAGE_BYTES;      // 196608
static_assert(SMEM_GEMM <= 232448, "smem too big");

// preproc grid split
static constexpr int QBLOCKS = Ndim;                // 8192 quant blocks
static constexpr int CBLOCKS = 2048;                // cvt blocks

// ------------------- scratch (device globals; no runtime alloc allowed) ----
__device__ __half g_xh[(size_t)Mdim * Kdim];   // x rounded to fp16
__device__ __half g_wq[(size_t)Ndim * Kdim];   // ternary weights in fp16
__device__ float  g_scale[Ndim];

// ------------------- device helpers ---------------------------------------
DEVINL uint32_t smem_u32(const void* p) {
    uint32_t a;
    asm("{ .reg .u64 t; cvta.to.shared.u64 t, %1; cvt.u32.u64 %0, t; }" : "=r"(a) : "l"(p));
    return a;
}
DEVINL uint32_t swz(uint32_t off) { return off ^ ((off >> 3) & 0x70); }

DEVINL void cp_async16(uint32_t s, const void* g) {
    asm volatile("cp.async.cg.shared.global [%0], [%1], 16;" :: "r"(s), "l"(g) : "memory");
}
DEVINL void cp_commit() { asm volatile("cp.async.commit_group;" ::: "memory"); }
template <int N> DEVINL void cp_wait() {
    asm volatile("cp.async.wait_group %0;" :: "n"(N) : "memory");
}

DEVINL void ldsm4(uint32_t* r, uint32_t a) {
    asm volatile("ldmatrix.sync.aligned.m8n8.x4.shared.b16 {%0,%1,%2,%3}, [%4];"
                 : "=r"(r[0]), "=r"(r[1]), "=r"(r[2]), "=r"(r[3]) : "r"(a));
}
DEVINL void mma16816(float* c, const uint32_t* a, uint32_t b0, uint32_t b1) {
    asm volatile(
        "mma.sync.aligned.m16n8k16.row.col.f32.f16.f16.f32 "
        "{%0,%1,%2,%3}, {%4,%5,%6,%7}, {%8,%9}, {%0,%1,%2,%3};"
        : "+f"(c[0]), "+f"(c[1]), "+f"(c[2]), "+f"(c[3])
        : "r"(a[0]), "r"(a[1]), "r"(a[2]), "r"(a[3]), "r"(b0), "r"(b1));
}

DEVINL uint32_t pack2h(float a, float b) {
    __half2 h = __floats2half2_rn(a, b);
    return *reinterpret_cast<uint32_t*>(&h);
}

// ------------------- fused preproc kernel ----------------------------------
// blocks [0, QBLOCKS):          per-row weight quantization
//   scale[o] = max(mean|w[o,:]|, 1e-5); wq = clip(rint(w/scale), -1, 1) -> fp16
// blocks [QBLOCKS, QBLOCKS+CBLOCKS): x -> fp16 (grid-stride)
__global__ void __launch_bounds__(256) preproc_kernel(
    const float* __restrict__ w, const float4* __restrict__ x,
    __half* __restrict__ wq, uint2* __restrict__ xh, float* __restrict__ scale)
{
    const int t = threadIdx.x;
    if (blockIdx.x < QBLOCKS) {
        const int row = blockIdx.x;
        const float4* wr = reinterpret_cast<const float4*>(w) + (size_t)row * (Kdim / 4);

        float4 v0 = wr[t];
        float4 v1 = wr[t + 256];
        float s = fabsf(v0.x) + fabsf(v0.y) + fabsf(v0.z) + fabsf(v0.w)
                + fabsf(v1.x) + fabsf(v1.y) + fabsf(v1.z) + fabsf(v1.w);
        #pragma unroll
        for (int o = 16; o > 0; o >>= 1) s += __shfl_xor_sync(0xffffffffu, s, o);

        __shared__ float red[8];
        __shared__ float s_bcast;
        if ((t & 31) == 0) red[t >> 5] = s;
        __syncthreads();
        if (t == 0) {
            float acc = 0.f;
            #pragma unroll
            for (int i = 0; i < 8; i++) acc += red[i];
            float sc = fmaxf(acc * (1.0f / Kdim), 1e-5f);
            s_bcast = sc;
            scale[row] = sc;
        }
        __syncthreads();
        const float sc = s_bcast;

        auto q = [&](float v) -> float {
            float r = rintf(__fdiv_rn(v, sc));   // IEEE div + round-half-even matches jnp.round
            return fminf(1.f, fmaxf(-1.f, r));
        };
        uint2* dst = reinterpret_cast<uint2*>(wq) + (size_t)row * (Kdim / 4);
        uint2 o0, o1;
        o0.x = pack2h(q(v0.x), q(v0.y)); o0.y = pack2h(q(v0.z), q(v0.w));
        o1.x = pack2h(q(v1.x), q(v1.y)); o1.y = pack2h(q(v1.z), q(v1.w));
        dst[t] = o0;
        dst[t + 256] = o1;
    } else {
        const int n4 = (Mdim * Kdim) / 4;
        for (int i = (blockIdx.x - QBLOCKS) * 256 + t; i < n4; i += CBLOCKS * 256) {
            float4 v = x[i];
            uint2 h;
            h.x = pack2h(v.x, v.y);
            h.y = pack2h(v.z, v.w);
            xh[i] = h;
        }
    }
}

// ------------------- GEMM kernel -------------------------------------------
__global__ void __launch_bounds__(256, 1) bitlinear_gemm(
    const __half* __restrict__ X, const __half* __restrict__ W,
    const float* __restrict__ scale, float* __restrict__ out)
{
    extern __shared__ char smem[];
    const uint32_t sb = smem_u32(smem);
    const int tid = threadIdx.x;
    const int lane = tid & 31, wid = tid >> 5;
    const int wm = wid >> 2, wn = wid & 3;            // 2x4 warp grid, warp tile 64x64
    const int m0 = blockIdx.y * BM, n0 = blockIdx.x * BN;

    // cp.async mapping: thread -> (row, 16B segment); 32 rows per pass
    const int lrow = tid >> 3, seg = tid & 7;
    const __half* gA = X + (size_t)(m0 + lrow) * Kdim + seg * 8;
    const __half* gB = W + (size_t)(n0 + lrow) * Kdim + seg * 8;
    const uint32_t swz_off = swz((uint32_t)(lrow * 128 + seg * 16)); // row&7 invariant under +32

    auto issue = [&](int s, int kc) {
        const uint32_t base = sb + s * STAGE_BYTES + swz_off;
        const __half* a = gA + kc * BK;
        const __half* b = gB + kc * BK;
        #pragma unroll
        for (int p = 0; p < 4; p++)
            cp_async16(base + p * 4096, a + (size_t)p * 32 * Kdim);
        #pragma unroll
        for (int p = 0; p < 8; p++)
            cp_async16(base + A_BYTES + p * 4096, b + (size_t)p * 32 * Kdim);
        cp_commit();
    };

    issue(0, 0); issue(1, 1); issue(2, 2);

    // per-lane ldmatrix address components (cutlass TN pattern, plain ldsm both sides)
    const int la7 = lane & 7;
    const int mA  = la7 + (((lane >> 3) & 1) << 3);
    const int khA = (lane >> 4) & 1;
    const int nB  = la7 + (((lane >> 4) & 1) << 3);
    const int khB = (lane >> 3) & 1;
    const uint32_t rowA = (uint32_t)(wm * 64 + mA) * 128;
    const uint32_t rowB = (uint32_t)(wn * 64 + nB) * 128;
    uint32_t colA[4], colB[4];
    #pragma unroll
    for (int ks = 0; ks < 4; ks++) {
        colA[ks] = (uint32_t)((ks * 32 + khA * 16) ^ (la7 << 4));
        colB[ks] = (uint32_t)((ks * 32 + khB * 16) ^ (la7 << 4));
    }

    float c[4][8][4];
    #pragma unroll
    for (int mt = 0; mt < 4; mt++)
        #pragma unroll
        for (int nt = 0; nt < 8; nt++)
            #pragma unroll
            for (int i = 0; i < 4; i++) c[mt][nt][i] = 0.f;

    // double-buffered register fragments
    uint32_t af[2][4][4], bf[2][4][4];
    auto ldfrag = [&](int buf, uint32_t sA, uint32_t sB, int ks) {
        #pragma unroll
        for (int mt = 0; mt < 4; mt++)
            ldsm4(af[buf][mt], sA + rowA + mt * 2048 + colA[ks]);
        #pragma unroll
        for (int bt = 0; bt < 4; bt++)
            ldsm4(bf[buf][bt], sB + rowB + bt * 2048 + colB[ks]);
    };

    cp_wait<STAGES - 2>();
    __syncthreads();
    ldfrag(0, sb, sb + A_BYTES, 0);     // stage 0, ks 0

    for (int kc = 0; kc < KCHUNKS; kc++) {
        const uint32_t sA = sb + (kc & (STAGES - 1)) * STAGE_BYTES;
        const uint32_t sB = sA + A_BYTES;
        const uint32_t nA = sb + ((kc + 1) & (STAGES - 1)) * STAGE_BYTES;

        // fill the stage vacated at the end of the previous chunk
        const int kn = kc + STAGES - 1;
        if (kn < KCHUNKS) issue(kn & (STAGES - 1), kn);
        else cp_commit();                         // keep group-count semantics in the tail

        #pragma unroll
        for (int ks = 0; ks < 4; ks++) {
            const int cur = ks & 1, nxt = cur ^ 1;
            if (ks < 3) ldfrag(nxt, sA, sB, ks + 1);

            // mma issued BEFORE the stage barrier at ks==3: the tensor pipe
            // drains asynchronously through cp_wait/bar (register operands only)
            #pragma unroll
            for (int mt = 0; mt < 4; mt++)
                #pragma unroll
                for (int nt = 0; nt < 8; nt++)
                    mma16816(c[mt][nt], af[cur][mt],
                             bf[cur][nt >> 1][(nt & 1) * 2], bf[cur][nt >> 1][(nt & 1) * 2 + 1]);

            if (ks == 3) {
                cp_wait<STAGES - 2>();            // next stage resident
                __syncthreads();                  // all smem reads of old stage done
                if (kc + 1 < KCHUNKS)
                    ldfrag(nxt, nA, nA + A_BYTES, 0);
            }
        }
    }

    // epilogue: apply per-output-column scale in fp32, vectorized float2 stores
    const int g = lane >> 2, t4 = lane & 3;
    #pragma unroll
    for (int nt = 0; nt < 8; nt++) {
        const int ncol = n0 + wn * 64 + nt * 8 + t4 * 2;
        const float2 s2 = *reinterpret_cast<const float2*>(scale + ncol);
        #pragma unroll
        for (int mt = 0; mt < 4; mt++) {
            const int r0 = m0 + wm * 64 + mt * 16 + g;
            float2 v0, v1;
            v0.x = c[mt][nt][0] * s2.x; v0.y = c[mt][nt][1] * s2.y;
            v1.x = c[mt][nt][2] * s2.x; v1.y = c[mt][nt][3] * s2.y;
            *reinterpret_cast<float2*>(out + (size_t)r0 * Ndim + ncol) = v0;
            *reinterpret_cast<float2*>(out + (size_t)(r0 + 8) * Ndim + ncol) = v1;
        }
    }
}

// ------------------- host side ---------------------------------------------
extern "C" void kernel_launch(void* const* d_in, const int* in_sizes, int n_in,
                              void* d_out, int out_size)
{
    const float* x = (const float*)d_in[0];    // [4,2048,2048]
    const float* w = (const float*)d_in[1];    // [8192,2048]
    float* out = (float*)d_out;                // [4,2048,8192]
    (void)in_sizes; (void)n_in; (void)out_size;

    void *p_xh = nullptr, *p_wq = nullptr, *p_scale = nullptr;
    cudaGetSymbolAddress(&p_xh, g_xh);
    cudaGetSymbolAddress(&p_wq, g_wq);
    cudaGetSymbolAddress(&p_scale, g_scale);

    preproc_kernel<<<QBLOCKS + CBLOCKS, 256>>>(
        w, (const float4*)x, (__half*)p_wq, (uint2*)p_xh, (float*)p_scale);

    cudaFuncSetAttribute(bitlinear_gemm, cudaFuncAttributeMaxDynamicSharedMemorySize, SMEM_GEMM);
    dim3 grid(Ndim / BN, Mdim / BM);   // (32, 64)
    bitlinear_gemm<<<grid, 256, SMEM_GEMM>>>(
        (const __half*)p_xh, (const __half*)p_wq, (const float*)p_scale, out);
}

// round 17
// speedup vs baseline: 1.3086x; 1.0533x over previous
#include <cuda_runtime.h>
#include <cuda_fp16.h>
#include <cstdint>

#define DEVINL __device__ __forceinline__

// Problem dims
static constexpr int Mdim = 8192;   // B*S = 4*2048
static constexpr int Ndim = 8192;   // D_OUT
static constexpr int Kdim = 2048;   // D_IN

// GEMM tiling (sm80-style mma.sync pipeline; tcgen05 unavailable at target sm_103)
// Block 128x128, 128 threads (2x2 warp grid, warp tile 64x64), BK=64,
// 3-stage cp.async, register double-buffering, 2 CTAs/SM so that per-SMSP the
// two resident warps belong to DIFFERENT CTAs and their stage barriers interleave.
static constexpr int BM = 128;
static constexpr int BN = 128;
static constexpr int BK = 64;                       // fp16 elems per chunk = 128 bytes/row
static constexpr int STAGES = 3;
static constexpr int KCHUNKS = Kdim / BK;           // 32
static constexpr int A_BYTES = BM * 128;            // 16384
static constexpr int B_BYTES = BN * 128;            // 16384
static constexpr int STAGE_BYTES = A_BYTES + B_BYTES;       // 32768
static constexpr int SMEM_GEMM = STAGES * STAGE_BYTES;      // 98304 (x2 CTAs = 196608/SM)
static_assert(2 * SMEM_GEMM <= 232448, "2 CTAs must fit in SM smem");

// preproc grid split
static constexpr int QBLOCKS = Ndim;                // 8192 quant blocks
static constexpr int CBLOCKS = 2048;                // cvt blocks

// ------------------- scratch (device globals; no runtime alloc allowed) ----
__device__ __half g_xh[(size_t)Mdim * Kdim];   // x rounded to fp16
__device__ __half g_wq[(size_t)Ndim * Kdim];   // ternary weights in fp16
__device__ float  g_scale[Ndim];

// ------------------- device helpers ---------------------------------------
DEVINL uint32_t smem_u32(const void* p) {
    uint32_t a;
    asm("{ .reg .u64 t; cvta.to.shared.u64 t, %1; cvt.u32.u64 %0, t; }" : "=r"(a) : "l"(p));
    return a;
}
DEVINL uint32_t swz(uint32_t off) { return off ^ ((off >> 3) & 0x70); }

DEVINL void cp_async16(uint32_t s, const void* g) {
    asm volatile("cp.async.cg.shared.global [%0], [%1], 16;" :: "r"(s), "l"(g) : "memory");
}
DEVINL void cp_commit() { asm volatile("cp.async.commit_group;" ::: "memory"); }
template <int N> DEVINL void cp_wait() {
    asm volatile("cp.async.wait_group %0;" :: "n"(N) : "memory");
}

DEVINL void ldsm4(uint32_t* r, uint32_t a) {
    asm volatile("ldmatrix.sync.aligned.m8n8.x4.shared.b16 {%0,%1,%2,%3}, [%4];"
                 : "=r"(r[0]), "=r"(r[1]), "=r"(r[2]), "=r"(r[3]) : "r"(a));
}
DEVINL void mma16816(float* c, const uint32_t* a, uint32_t b0, uint32_t b1) {
    asm volatile(
        "mma.sync.aligned.m16n8k16.row.col.f32.f16.f16.f32 "
        "{%0,%1,%2,%3}, {%4,%5,%6,%7}, {%8,%9}, {%0,%1,%2,%3};"
        : "+f"(c[0]), "+f"(c[1]), "+f"(c[2]), "+f"(c[3])
        : "r"(a[0]), "r"(a[1]), "r"(a[2]), "r"(a[3]), "r"(b0), "r"(b1));
}

DEVINL uint32_t pack2h(float a, float b) {
    __half2 h = __floats2half2_rn(a, b);
    return *reinterpret_cast<uint32_t*>(&h);
}

// ------------------- fused preproc kernel ----------------------------------
// blocks [0, QBLOCKS):               per-row weight quantization
//   scale[o] = max(mean|w[o,:]|, 1e-5); wq = clip(rint(w/scale), -1, 1) -> fp16
// blocks [QBLOCKS, QBLOCKS+CBLOCKS): x -> fp16 (grid-stride)
__global__ void __launch_bounds__(256) preproc_kernel(
    const float* __restrict__ w, const float4* __restrict__ x,
    __half* __restrict__ wq, uint2* __restrict__ xh, float* __restrict__ scale)
{
    const int t = threadIdx.x;
    if (blockIdx.x < QBLOCKS) {
        const int row = blockIdx.x;
        const float4* wr = reinterpret_cast<const float4*>(w) + (size_t)row * (Kdim / 4);

        float4 v0 = wr[t];
        float4 v1 = wr[t + 256];
        float s = fabsf(v0.x) + fabsf(v0.y) + fabsf(v0.z) + fabsf(v0.w)
                + fabsf(v1.x) + fabsf(v1.y) + fabsf(v1.z) + fabsf(v1.w);
        #pragma unroll
        for (int o = 16; o > 0; o >>= 1) s += __shfl_xor_sync(0xffffffffu, s, o);

        __shared__ float red[8];
        __shared__ float s_bcast;
        if ((t & 31) == 0) red[t >> 5] = s;
        __syncthreads();
        if (t == 0) {
            float acc = 0.f;
            #pragma unroll
            for (int i = 0; i < 8; i++) acc += red[i];
            float sc = fmaxf(acc * (1.0f / Kdim), 1e-5f);
            s_bcast = sc;
            scale[row] = sc;
        }
        __syncthreads();
        const float sc = s_bcast;

        auto q = [&](float v) -> float {
            float r = rintf(__fdiv_rn(v, sc));   // IEEE div + round-half-even matches jnp.round
            return fminf(1.f, fmaxf(-1.f, r));
        };
        uint2* dst = reinterpret_cast<uint2*>(wq) + (size_t)row * (Kdim / 4);
        uint2 o0, o1;
        o0.x = pack2h(q(v0.x), q(v0.y)); o0.y = pack2h(q(v0.z), q(v0.w));
        o1.x = pack2h(q(v1.x), q(v1.y)); o1.y = pack2h(q(v1.z), q(v1.w));
        dst[t] = o0;
        dst[t + 256] = o1;
    } else {
        const int n4 = (Mdim * Kdim) / 4;
        for (int i = (blockIdx.x - QBLOCKS) * 256 + t; i < n4; i += CBLOCKS * 256) {
            float4 v = x[i];
            uint2 h;
            h.x = pack2h(v.x, v.y);
            h.y = pack2h(v.z, v.w);
            xh[i] = h;
        }
    }
}

// ------------------- GEMM kernel -------------------------------------------
__global__ void __launch_bounds__(128, 2) bitlinear_gemm(
    const __half* __restrict__ X, const __half* __restrict__ W,
    const float* __restrict__ scale, float* __restrict__ out)
{
    extern __shared__ char smem[];
    const uint32_t sb = smem_u32(smem);
    const int tid = threadIdx.x;
    const int lane = tid & 31, wid = tid >> 5;
    const int wm = wid >> 1, wn = wid & 1;            // 2x2 warp grid, warp tile 64x64
    const int m0 = blockIdx.y * BM, n0 = blockIdx.x * BN;

    // cp.async mapping: thread -> (row, 16B segment); 16 rows per pass, 8 passes/tile
    const int lrow = tid >> 3, seg = tid & 7;
    const __half* gA = X + (size_t)(m0 + lrow) * Kdim + seg * 8;
    const __half* gB = W + (size_t)(n0 + lrow) * Kdim + seg * 8;
    const uint32_t swz_off = swz((uint32_t)(lrow * 128 + seg * 16)); // row&7 invariant under +16

    auto issue = [&](int s, int kc) {
        const uint32_t base = sb + s * STAGE_BYTES + swz_off;
        const __half* a = gA + kc * BK;
        const __half* b = gB + kc * BK;
        #pragma unroll
        for (int p = 0; p < 8; p++)
            cp_async16(base + p * 2048, a + (size_t)p * 16 * Kdim);
        #pragma unroll
        for (int p = 0; p < 8; p++)
            cp_async16(base + A_BYTES + p * 2048, b + (size_t)p * 16 * Kdim);
        cp_commit();
    };

    issue(0, 0); issue(1, 1);

    // per-lane ldmatrix address components (cutlass TN pattern, plain ldsm both sides)
    const int la7 = lane & 7;
    const int mA  = la7 + (((lane >> 3) & 1) << 3);
    const int khA = (lane >> 4) & 1;
    const int nB  = la7 + (((lane >> 4) & 1) << 3);
    const int khB = (lane >> 3) & 1;
    const uint32_t rowA = (uint32_t)(wm * 64 + mA) * 128;
    const uint32_t rowB = (uint32_t)(wn * 64 + nB) * 128;
    uint32_t colA[4], colB[4];
    #pragma unroll
    for (int ks = 0; ks < 4; ks++) {
        colA[ks] = (uint32_t)((ks * 32 + khA * 16) ^ (la7 << 4));
        colB[ks] = (uint32_t)((ks * 32 + khB * 16) ^ (la7 << 4));
    }

    float c[4][8][4];
    #pragma unroll
    for (int mt = 0; mt < 4; mt++)
        #pragma unroll
        for (int nt = 0; nt < 8; nt++)
            #pragma unroll
            for (int i = 0; i < 4; i++) c[mt][nt][i] = 0.f;

    // double-buffered register fragments
    uint32_t af[2][4][4], bf[2][4][4];
    auto ldfrag = [&](int buf, uint32_t sA, uint32_t sB, int ks) {
        #pragma unroll
        for (int mt = 0; mt < 4; mt++)
            ldsm4(af[buf][mt], sA + rowA + mt * 2048 + colA[ks]);
        #pragma unroll
        for (int bt = 0; bt < 4; bt++)
            ldsm4(bf[buf][bt], sB + rowB + bt * 2048 + colB[ks]);
    };

    cp_wait<1>();
    __syncthreads();
    ldfrag(0, sb, sb + A_BYTES, 0);     // stage 0, ks 0

    int scur = 0;
    for (int kc = 0; kc < KCHUNKS; kc++) {
        const uint32_t sA = sb + scur * STAGE_BYTES;
        const uint32_t sB = sA + A_BYTES;
        const int snxt  = (scur + 1 == STAGES) ? 0 : scur + 1;
        const int sfill = (snxt + 1 == STAGES) ? 0 : snxt + 1;   // vacated by chunk kc-1
        const uint32_t nA = sb + snxt * STAGE_BYTES;

        const int kn = kc + STAGES - 1;
        if (kn < KCHUNKS) issue(sfill, kn);
        else cp_commit();                         // keep group-count semantics in the tail

        #pragma unroll
        for (int ks = 0; ks < 4; ks++) {
            const int cur = ks & 1, nxt = cur ^ 1;
            if (ks < 3) ldfrag(nxt, sA, sB, ks + 1);

            // mma issued BEFORE the stage barrier at ks==3: the tensor pipe
            // drains asynchronously through cp_wait/bar (register operands only)
            #pragma unroll
            for (int mt = 0; mt < 4; mt++)
                #pragma unroll
                for (int nt = 0; nt < 8; nt++)
                    mma16816(c[mt][nt], af[cur][mt],
                             bf[cur][nt >> 1][(nt & 1) * 2], bf[cur][nt >> 1][(nt & 1) * 2 + 1]);

            if (ks == 3) {
                cp_wait<1>();                     // next stage resident
                __syncthreads();                  // all smem reads of old stage done
                if (kc + 1 < KCHUNKS)
                    ldfrag(nxt, nA, nA + A_BYTES, 0);
            }
        }
        scur = snxt;
    }

    // epilogue: apply per-output-column scale in fp32, vectorized float2 stores
    const int g = lane >> 2, t4 = lane & 3;
    #pragma unroll
    for (int nt = 0; nt < 8; nt++) {
        const int ncol = n0 + wn * 64 + nt * 8 + t4 * 2;
        const float2 s2 = *reinterpret_cast<const float2*>(scale + ncol);
        #pragma unroll
        for (int mt = 0; mt < 4; mt++) {
            const int r0 = m0 + wm * 64 + mt * 16 + g;
            float2 v0, v1;
            v0.x = c[mt][nt][0] * s2.x; v0.y = c[mt][nt][1] * s2.y;
            v1.x = c[mt][nt][2] * s2.x; v1.y = c[mt][nt][3] * s2.y;
            *reinterpret_cast<float2*>(out + (size_t)r0 * Ndim + ncol) = v0;
            *reinterpret_cast<float2*>(out + (size_t)(r0 + 8) * Ndim + ncol) = v1;
        }
    }
}

// ------------------- host side ---------------------------------------------
extern "C" void kernel_launch(void* const* d_in, const int* in_sizes, int n_in,
                              void* d_out, int out_size)
{
    const float* x = (const float*)d_in[0];    // [4,2048,2048]
    const float* w = (const float*)d_in[1];    // [8192,2048]
    float* out = (float*)d_out;                // [4,2048,8192]
    (void)in_sizes; (void)n_in; (void)out_size;

    void *p_xh = nullptr, *p_wq = nullptr, *p_scale = nullptr;
    cudaGetSymbolAddress(&p_xh, g_xh);
    cudaGetSymbolAddress(&p_wq, g_wq);
    cudaGetSymbolAddress(&p_scale, g_scale);

    preproc_kernel<<<QBLOCKS + CBLOCKS, 256>>>(
        w, (const float4*)x, (__half*)p_wq, (uint2*)p_xh, (float*)p_scale);

    cudaFuncSetAttribute(bitlinear_gemm, cudaFuncAttributeMaxDynamicSharedMemorySize, SMEM_GEMM);
    dim3 grid(Ndim / BN, Mdim / BM);   // (64, 64)
    bitlinear_gemm<<<grid, 128, SMEM_GEMM>>>(
        (const __half*)p_xh, (const __half*)p_wq, (const float*)p_scale, out);
}